// round 13
// baseline (speedup 1.0000x reference)
#include <cuda_runtime.h>
#include <cuda_bf16.h>
#include <cstdint>

// Problem constants
#define B_   4
#define S_   2048
#define D_   1024
#define NC_  16
#define NK_  32768
#define R_   128
#define TK_  8
#define NTOK (B_*S_)          // 8192 tokens
#define NSPLIT4 4
#define NSPL4 (NK_/NSPLIT4)   // 8192 knowledge rows per split
#define CHN  32               // knowledge rows per chunk
#define NCH  (NSPL4/CHN)      // 256 chunks
#define NCAND 8               // top-8 per split -> 32 candidates/token

#define SCALE_ 0.08838834764831845f

#define QSTR 136              // bf16 smem row stride (Q/K tiles)
#define SSTR 68               // fp32 smem row stride (score tile)

// smem offsets (bytes) — 64-token tile variant
#define QS_OFF 0
#define KS_OFF (64*QSTR*2)               // 17408
#define KSZ    (32*QSTR*2)               // 8704 per K buffer
#define SS_OFF (KS_OFF + 2*KSZ)          // 34816
#define SMEM_SC (SS_OFF + 64*SSTR*4)     // 52224  -> 4 CTAs/SM

// ---------------- scratch ----------------
__device__ float          g_SC [B_*D_*R_];
__device__ float          g_Q  [NTOK*R_];
__device__ __nv_bfloat16  g_Qbf[NTOK*R_];
__device__ __nv_bfloat16  g_Kbf[NK_*R_];
__device__ int            g_ci [NTOK*NSPLIT4*NCAND];

// ---------------- PTX helpers ----------------
__device__ __forceinline__ uint32_t smem_u32(const void* p) {
    uint32_t a;
    asm("{ .reg .u64 t; cvta.to.shared.u64 t, %1; cvt.u32.u64 %0, t; }" : "=r"(a) : "l"(p));
    return a;
}
__device__ __forceinline__ void ldsm_x4(uint32_t& r0, uint32_t& r1, uint32_t& r2, uint32_t& r3,
                                        uint32_t addr) {
    asm volatile("ldmatrix.sync.aligned.m8n8.x4.shared.b16 {%0,%1,%2,%3}, [%4];"
                 : "=r"(r0), "=r"(r1), "=r"(r2), "=r"(r3) : "r"(addr));
}
__device__ __forceinline__ void cp_async16(uint32_t saddr, const void* gptr) {
    asm volatile("cp.async.cg.shared.global [%0], [%1], 16;" :: "r"(saddr), "l"(gptr));
}
__device__ __forceinline__ void cp_commit() { asm volatile("cp.async.commit_group;"); }
__device__ __forceinline__ void cp_wait0()  { asm volatile("cp.async.wait_group 0;" ::: "memory"); }

__device__ __forceinline__ void mma_bf16(float c[4], uint32_t a0, uint32_t a1, uint32_t a2,
                                         uint32_t a3, uint32_t b0, uint32_t b1) {
    asm volatile(
        "mma.sync.aligned.m16n8k16.row.col.f32.bf16.bf16.f32 "
        "{%0,%1,%2,%3}, {%4,%5,%6,%7}, {%8,%9}, {%0,%1,%2,%3};"
        : "+f"(c[0]), "+f"(c[1]), "+f"(c[2]), "+f"(c[3])
        : "r"(a0), "r"(a1), "r"(a2), "r"(a3), "r"(b0), "r"(b1));
}

// packed fp32x2 FMA (exact per-lane fp32 rounding)
__device__ __forceinline__ unsigned long long ffma2(unsigned long long a,
                                                    unsigned long long b,
                                                    unsigned long long c) {
    unsigned long long d;
    asm("fma.rn.f32x2 %0, %1, %2, %3;" : "=l"(d) : "l"(a), "l"(b), "l"(c));
    return d;
}
__device__ __forceinline__ unsigned long long pack_dup(float v) {
    unsigned long long d;
    asm("mov.b64 %0, {%1, %2};" : "=l"(d) : "f"(v), "f"(v));
    return d;
}
__device__ __forceinline__ void unpack2(unsigned long long d, float& lo, float& hi) {
    asm("mov.b64 {%0, %1}, %2;" : "=f"(lo), "=f"(hi) : "l"(d));
}

// ---------------- K1: shared_compress ----------------
__global__ void sc_kernel(const float* __restrict__ mw, const float* __restrict__ cn) {
    int b = blockIdx.x, d = blockIdx.y, r = threadIdx.x;
    float acc = 0.f;
#pragma unroll
    for (int n = 0; n < NC_; n++)
        acc = fmaf(mw[b*NC_ + n], cn[((size_t)n*D_ + d)*R_ + r], acc);
    g_SC[((size_t)b*D_ + d)*R_ + r] = acc;
}

// ---------------- K1b: convert K -> bf16 ----------------
__global__ void kbf_kernel(const float4* __restrict__ kK) {
    int i = blockIdx.x*blockDim.x + threadIdx.x;
    float4 v = kK[i];
    __nv_bfloat16* d = g_Kbf + (size_t)i*4;
    d[0] = __float2bfloat16(v.x); d[1] = __float2bfloat16(v.y);
    d[2] = __float2bfloat16(v.z); d[3] = __float2bfloat16(v.w);
}

// ---------------- K2: Q projection (fp32 exact, d-ascending chain, packed FFMA2) ----------------
__global__ void q_kernel(const float* __restrict__ x) {
    __shared__ float xs[32][68];
    __shared__ float scs[32][128];
    int tid = threadIdx.x;
    int b = blockIdx.y, s0 = blockIdx.x*64;

    unsigned long long acc[4][4];
#pragma unroll
    for (int i = 0; i < 4; i++)
#pragma unroll
        for (int j = 0; j < 4; j++) acc[i][j] = 0ull;

    int tx = (tid & 15)*8;
    int ty = (tid >> 4)*4;

    for (int d0 = 0; d0 < D_; d0 += 32) {
#pragma unroll
        for (int i = 0; i < 2; i++) {
            int idx = tid + 256*i;
            int s = idx >> 3, g = idx & 7;
            float4 v = *(const float4*)(x + (((size_t)b*S_) + s0 + s)*D_ + d0 + 4*g);
            xs[4*g+0][s] = v.x; xs[4*g+1][s] = v.y; xs[4*g+2][s] = v.z; xs[4*g+3][s] = v.w;
        }
#pragma unroll
        for (int i = 0; i < 4; i++) {
            int idx = tid + 256*i;
            int dd = idx >> 5, g = idx & 31;
            *(float4*)&scs[dd][4*g] = *(const float4*)(g_SC + (((size_t)b*D_) + d0 + dd)*R_ + 4*g);
        }
        __syncthreads();
#pragma unroll
        for (int dd = 0; dd < 32; dd++) {
            unsigned long long q[4];
#pragma unroll
            for (int i = 0; i < 4; i++) q[i] = pack_dup(xs[dd][ty + i]);
            float4 ka = *(float4*)&scs[dd][tx];
            float4 kb = *(float4*)&scs[dd][tx+4];
            unsigned long long k2[4];
            k2[0] = *(unsigned long long*)&ka.x;
            k2[1] = *(unsigned long long*)&ka.z;
            k2[2] = *(unsigned long long*)&kb.x;
            k2[3] = *(unsigned long long*)&kb.z;
#pragma unroll
            for (int i = 0; i < 4; i++)
#pragma unroll
                for (int j = 0; j < 4; j++)
                    acc[i][j] = ffma2(q[i], k2[j], acc[i][j]);
        }
        __syncthreads();
    }
#pragma unroll
    for (int i = 0; i < 4; i++) {
        int tok = b*S_ + s0 + ty + i;
#pragma unroll
        for (int j = 0; j < 4; j++) {
            float lo, hi;
            unpack2(acc[i][j], lo, hi);
            g_Q  [(size_t)tok*R_ + tx + 2*j    ] = lo;
            g_Q  [(size_t)tok*R_ + tx + 2*j + 1] = hi;
            g_Qbf[(size_t)tok*R_ + tx + 2*j    ] = __float2bfloat16(lo);
            g_Qbf[(size_t)tok*R_ + tx + 2*j + 1] = __float2bfloat16(hi);
        }
    }
}

// ---------------- K3: bf16 mma.sync scores, 64-token tiles, 4 CTAs/SM ----------------
__global__ void __launch_bounds__(128, 4) score_mma_kernel() {
    extern __shared__ char sm[];
    __nv_bfloat16 (*Qs)[QSTR] = (__nv_bfloat16(*)[QSTR])(sm + QS_OFF);
    float (*Ss)[SSTR]         = (float(*)[SSTR])(sm + SS_OFF);

    int tid  = threadIdx.x;
    int wid  = tid >> 5;
    int lane = tid & 31;
    int t8   = lane & 7;
    int tl   = lane >> 3;

    int wm = wid & 1;            // m half (32 tokens)
    int wn = wid >> 1;           // n half (16 knowledge)

    int token0 = blockIdx.x * 64;
    int split  = blockIdx.y;
    int nbase0 = split * NSPL4;

    uint32_t smbase = smem_u32(sm);
    uint32_t qs_u32 = smbase + QS_OFF;
    uint32_t ks_u32 = smbase + KS_OFF;

    // per-thread ldmatrix address offsets (bytes)
    uint32_t aoff[2];
#pragma unroll
    for (int mf = 0; mf < 2; mf++)
        aoff[mf] = (uint32_t)((wm*32 + mf*16 + (tl & 1)*8 + t8)*QSTR + (tl >> 1)*8) * 2;
    uint32_t boff = (uint32_t)((wn*16 + (tl >> 1)*8 + t8)*QSTR + (tl & 1)*8) * 2;

    // ---- preload Q tile (64 tokens x 128 bf16): 1024 uint4, 8 per thread
    {
        const uint4* src = (const uint4*)(g_Qbf + (size_t)token0 * R_);
#pragma unroll
        for (int i = 0; i < 8; i++) {
            int idx = tid + 128*i;
            int row = idx >> 4, c = idx & 15;
            *(uint4*)&Qs[row][c*8] = src[idx];
        }
    }
    // ---- preload first K chunk via cp.async: 512 uint4, 4 per thread
    {
        const uint4* src = (const uint4*)(g_Kbf + (size_t)nbase0 * R_);
#pragma unroll
        for (int i = 0; i < 4; i++) {
            int idx = tid + 128*i;
            int row = idx >> 4, c = idx & 15;
            cp_async16(ks_u32 + (uint32_t)(row*QSTR + c*8)*2, src + idx);
        }
        cp_commit();
    }

    int tok  = tid & 63;
    int half = tid >> 6;

    float ts[NCAND]; int ti[NCAND];
#pragma unroll
    for (int k = 0; k < NCAND; k++) { ts[k] = -3.402823466e38f; ti[k] = 0; }

    for (int ch = 0; ch < NCH; ch++) {
        int p = ch & 1;
        cp_wait0();
        __syncthreads();   // K[p] arrived; previous scan of Ss done

        // ---- prefetch next K chunk into K[p^1]
        if (ch + 1 < NCH) {
            const uint4* src = (const uint4*)(g_Kbf + (size_t)(nbase0 + (ch+1)*CHN) * R_);
            uint32_t dst = ks_u32 + (uint32_t)(p ^ 1)*KSZ;
#pragma unroll
            for (int i = 0; i < 4; i++) {
                int idx = tid + 128*i;
                int row = idx >> 4, c = idx & 15;
                cp_async16(dst + (uint32_t)(row*QSTR + c*8)*2, src + idx);
            }
        }
        cp_commit();

        // ---- MMA phase: warp tile 32m x 16n, k=128 in 8 steps (ldmatrix)
        float c[2][2][4];
#pragma unroll
        for (int mf = 0; mf < 2; mf++)
#pragma unroll
            for (int nf = 0; nf < 2; nf++)
#pragma unroll
                for (int e = 0; e < 4; e++) c[mf][nf][e] = 0.f;

        uint32_t kbuf = ks_u32 + (uint32_t)p*KSZ;
#pragma unroll
        for (int ks = 0; ks < 8; ks++) {
            uint32_t kb = (uint32_t)(ks*16)*2;
            uint32_t b0, b1, b2, b3;
            ldsm_x4(b0, b1, b2, b3, kbuf + boff + kb);
            uint32_t a[2][4];
#pragma unroll
            for (int mf = 0; mf < 2; mf++)
                ldsm_x4(a[mf][0], a[mf][1], a[mf][2], a[mf][3], qs_u32 + aoff[mf] + kb);
#pragma unroll
            for (int mf = 0; mf < 2; mf++) {
                mma_bf16(c[mf][0], a[mf][0], a[mf][1], a[mf][2], a[mf][3], b0, b1);
                mma_bf16(c[mf][1], a[mf][0], a[mf][1], a[mf][2], a[mf][3], b2, b3);
            }
        }
        // ---- dump C fragments to score tile
        {
            int g = lane >> 2, tig = lane & 3;
#pragma unroll
            for (int mf = 0; mf < 2; mf++) {
#pragma unroll
                for (int nf = 0; nf < 2; nf++) {
                    int row = wm*32 + mf*16 + g;
                    int col = wn*16 + nf*8 + tig*2;
                    *(float2*)&Ss[row    ][col] = make_float2(c[mf][nf][0], c[mf][nf][1]);
                    *(float2*)&Ss[row + 8][col] = make_float2(c[mf][nf][2], c[mf][nf][3]);
                }
            }
        }
        __syncthreads();   // Ss ready

        // ---- all 128 threads scan: token = tid&63, cols half*16..half*16+15
        {
            int nb = nbase0 + ch*CHN + half*16;
            const float* srow = &Ss[tok][half*16];
#pragma unroll 4
            for (int n4 = 0; n4 < 4; n4++) {
                float4 v = *(const float4*)(srow + 4*n4);
                float vv[4] = {v.x, v.y, v.z, v.w};
#pragma unroll
                for (int u = 0; u < 4; u++) {
                    float s = vv[u];
                    if (s > ts[NCAND-1]) {
                        int ni = nb + 4*n4 + u;
#pragma unroll
                        for (int k = 0; k < NCAND; k++) {
                            if (s > ts[k]) {
                                float tv = ts[k]; ts[k] = s; s = tv;
                                int tn = ti[k]; ti[k] = ni; ni = tn;
                            }
                        }
                    }
                }
            }
        }
    }

    // ---- merge the two halves' top-8 lists
    __syncthreads();
    if (tid >= 64) {
#pragma unroll
        for (int k = 0; k < NCAND; k++) {
            Ss[tok][k] = ts[k];
            ((int*)&Ss[tok][16])[k] = ti[k];
        }
    }
    __syncthreads();
    if (tid < 64) {
#pragma unroll
        for (int k2 = 0; k2 < NCAND; k2++) {
            float s = Ss[tok][k2];
            int  ni = ((int*)&Ss[tok][16])[k2];
            if (s > ts[NCAND-1]) {
#pragma unroll
                for (int k = 0; k < NCAND; k++) {
                    if (s > ts[k]) {
                        float tv = ts[k]; ts[k] = s; s = tv;
                        int tn = ti[k]; ti[k] = ni; ni = tn;
                    }
                }
            }
        }
        int gtok = token0 + tok;
#pragma unroll
        for (int k = 0; k < NCAND; k++)
            g_ci[((size_t)gtok*NSPLIT4 + split)*NCAND + k] = ti[k];
    }
}

// ---------------- K4: fused exact fp32 rescore + softmax + V gather (one block per token) ----------------
__global__ void rescore_gather_kernel(const float* __restrict__ kK,
                                      const float4* __restrict__ V4,
                                      float* __restrict__ out, int out_size) {
    int t = blockIdx.x;
    __shared__ float qs[128];
    __shared__ float ws[TK_];
    __shared__ int   is[TK_];
    int tid = threadIdx.x;

    if (tid < 128) qs[tid] = g_Q[(size_t)t*R_ + tid];
    __syncthreads();

    if (tid < 32) {
        int lane = tid;
        int cand = g_ci[(size_t)t*32 + lane];
        const float4* kr = (const float4*)(kK + (size_t)cand*R_);
        float acc = 0.f;
#pragma unroll
        for (int r4 = 0; r4 < 32; r4++) {
            float4 k4 = kr[r4];
            const float* q4 = &qs[4*r4];
            acc = fmaf(q4[0], k4.x, acc);
            acc = fmaf(q4[1], k4.y, acc);
            acc = fmaf(q4[2], k4.z, acc);
            acc = fmaf(q4[3], k4.w, acc);
        }
        float v = acc; int id = cand;
        float selv[TK_]; int seli[TK_];
#pragma unroll
        for (int k = 0; k < TK_; k++) {
            float bv = v; int bi = id;
#pragma unroll
            for (int off = 16; off > 0; off >>= 1) {
                float ov = __shfl_xor_sync(0xffffffffu, bv, off);
                int   oi = __shfl_xor_sync(0xffffffffu, bi, off);
                if (ov > bv || (ov == bv && oi < bi)) { bv = ov; bi = oi; }
            }
            selv[k] = bv; seli[k] = bi;
            if (id == bi) v = -3.402823466e38f;
        }
        float sv0 = selv[0] * SCALE_;
        float e[TK_]; float sum = 0.f;
#pragma unroll
        for (int k = 0; k < TK_; k++) { e[k] = expf(selv[k]*SCALE_ - sv0); sum += e[k]; }

        const int NBSD = B_*S_*D_;
        bool extended = (out_size >= NBSD + 2*NTOK*TK_);
        if (lane < TK_) {
            float w = e[lane] / sum;
            ws[lane] = w;
            is[lane] = seli[lane];
            if (extended) {
                out[NBSD + (size_t)t*TK_ + lane]            = (float)seli[lane];
                out[NBSD + NTOK*TK_ + (size_t)t*TK_ + lane] = w;
            }
        }
    }
    __syncthreads();

    int d4 = tid;                 // 0..255
    float4 acc = make_float4(0.f, 0.f, 0.f, 0.f);
#pragma unroll
    for (int k = 0; k < TK_; k++) {
        float w  = ws[k];
        float4 v = V4[(size_t)is[k]*(D_/4) + d4];
        acc.x = fmaf(w, v.x, acc.x);
        acc.y = fmaf(w, v.y, acc.y);
        acc.z = fmaf(w, v.z, acc.z);
        acc.w = fmaf(w, v.w, acc.w);
    }
    ((float4*)out)[(size_t)t*(D_/4) + d4] = acc;
}

// ---------------- launch ----------------
extern "C" void kernel_launch(void* const* d_in, const int* in_sizes, int n_in,
                              void* d_out, int out_size) {
    const float* x  = (const float*)d_in[0];
    const float* mw = (const float*)d_in[1];
    const float* cn = (const float*)d_in[2];
    const float* kK = (const float*)d_in[3];
    const float* kV = (const float*)d_in[4];
    float* out = (float*)d_out;

    cudaFuncSetAttribute(score_mma_kernel, cudaFuncAttributeMaxDynamicSharedMemorySize, SMEM_SC);

    sc_kernel<<<dim3(B_, D_), R_>>>(mw, cn);
    kbf_kernel<<<(NK_*R_/4)/256, 256>>>((const float4*)kK);
    q_kernel<<<dim3(S_/64, B_), 256>>>(x);
    score_mma_kernel<<<dim3(NTOK/64, NSPLIT4), 128, SMEM_SC>>>();
    rescore_gather_kernel<<<NTOK, 256>>>(kK, (const float4*)kV, out, out_size);
}

// round 14
// speedup vs baseline: 1.0419x; 1.0419x over previous
#include <cuda_runtime.h>
#include <cuda_bf16.h>
#include <cstdint>

// Problem constants
#define B_   4
#define S_   2048
#define D_   1024
#define NC_  16
#define NK_  32768
#define R_   128
#define TK_  8
#define NTOK (B_*S_)          // 8192 tokens
#define NSPLIT4 4
#define NSPL4 (NK_/NSPLIT4)   // 8192 knowledge rows per split
#define CHN  64               // knowledge rows per chunk
#define NCH  (NSPL4/CHN)      // 128 chunks
#define NCAND 8               // top-8 per split -> 32 candidates/token

#define SCALE_ 0.08838834764831845f

#define QSTR 136              // bf16 smem row stride (Q/K tiles)
#define SSTR 68               // fp32 smem row stride (score tile)

// smem offsets (bytes)
#define QS_OFF 0
#define KS_OFF (128*QSTR*2)              // 34816
#define KSZ    (64*QSTR*2)               // 17408 per K buffer
#define SS_OFF (KS_OFF + 2*KSZ)          // 69632
#define SMEM_SC (SS_OFF + 128*SSTR*4)    // 104448  -> 2 CTAs/SM

// ---------------- scratch ----------------
__device__ float          g_SC [B_*D_*R_];
__device__ float          g_Q  [NTOK*R_];
__device__ __nv_bfloat16  g_Qbf[NTOK*R_];
__device__ __nv_bfloat16  g_Kbf[NK_*R_];
__device__ int            g_ci [NTOK*NSPLIT4*NCAND];

// ---------------- PTX helpers ----------------
__device__ __forceinline__ uint32_t smem_u32(const void* p) {
    uint32_t a;
    asm("{ .reg .u64 t; cvta.to.shared.u64 t, %1; cvt.u32.u64 %0, t; }" : "=r"(a) : "l"(p));
    return a;
}
__device__ __forceinline__ void ldsm_x4(uint32_t& r0, uint32_t& r1, uint32_t& r2, uint32_t& r3,
                                        uint32_t addr) {
    asm volatile("ldmatrix.sync.aligned.m8n8.x4.shared.b16 {%0,%1,%2,%3}, [%4];"
                 : "=r"(r0), "=r"(r1), "=r"(r2), "=r"(r3) : "r"(addr));
}
__device__ __forceinline__ void cp_async16(uint32_t saddr, const void* gptr) {
    asm volatile("cp.async.cg.shared.global [%0], [%1], 16;" :: "r"(saddr), "l"(gptr));
}
__device__ __forceinline__ void cp_commit() { asm volatile("cp.async.commit_group;"); }
__device__ __forceinline__ void cp_wait0()  { asm volatile("cp.async.wait_group 0;" ::: "memory"); }

__device__ __forceinline__ void mma_bf16(float c[4], uint32_t a0, uint32_t a1, uint32_t a2,
                                         uint32_t a3, uint32_t b0, uint32_t b1) {
    asm volatile(
        "mma.sync.aligned.m16n8k16.row.col.f32.bf16.bf16.f32 "
        "{%0,%1,%2,%3}, {%4,%5,%6,%7}, {%8,%9}, {%0,%1,%2,%3};"
        : "+f"(c[0]), "+f"(c[1]), "+f"(c[2]), "+f"(c[3])
        : "r"(a0), "r"(a1), "r"(a2), "r"(a3), "r"(b0), "r"(b1));
}

// packed fp32x2 FMA (exact per-lane fp32 rounding)
__device__ __forceinline__ unsigned long long ffma2(unsigned long long a,
                                                    unsigned long long b,
                                                    unsigned long long c) {
    unsigned long long d;
    asm("fma.rn.f32x2 %0, %1, %2, %3;" : "=l"(d) : "l"(a), "l"(b), "l"(c));
    return d;
}
__device__ __forceinline__ unsigned long long pack_dup(float v) {
    unsigned long long d;
    asm("mov.b64 %0, {%1, %2};" : "=l"(d) : "f"(v), "f"(v));
    return d;
}
__device__ __forceinline__ void unpack2(unsigned long long d, float& lo, float& hi) {
    asm("mov.b64 {%0, %1}, %2;" : "=f"(lo), "=f"(hi) : "l"(d));
}

// ---------------- K1: shared_compress ----------------
__global__ void sc_kernel(const float* __restrict__ mw, const float* __restrict__ cn) {
    int b = blockIdx.x, d = blockIdx.y, r = threadIdx.x;
    float acc = 0.f;
#pragma unroll
    for (int n = 0; n < NC_; n++)
        acc = fmaf(mw[b*NC_ + n], cn[((size_t)n*D_ + d)*R_ + r], acc);
    g_SC[((size_t)b*D_ + d)*R_ + r] = acc;
}

// ---------------- K1b: convert K -> bf16 ----------------
__global__ void kbf_kernel(const float4* __restrict__ kK) {
    int i = blockIdx.x*blockDim.x + threadIdx.x;
    float4 v = kK[i];
    __nv_bfloat16* d = g_Kbf + (size_t)i*4;
    d[0] = __float2bfloat16(v.x); d[1] = __float2bfloat16(v.y);
    d[2] = __float2bfloat16(v.z); d[3] = __float2bfloat16(v.w);
}

// ---------------- K2: Q projection (fp32 exact, d-ascending chain, packed FFMA2) ----------------
__global__ void q_kernel(const float* __restrict__ x) {
    __shared__ float xs[32][68];
    __shared__ float scs[32][128];
    int tid = threadIdx.x;
    int b = blockIdx.y, s0 = blockIdx.x*64;

    unsigned long long acc[4][4];
#pragma unroll
    for (int i = 0; i < 4; i++)
#pragma unroll
        for (int j = 0; j < 4; j++) acc[i][j] = 0ull;

    int tx = (tid & 15)*8;
    int ty = (tid >> 4)*4;

    for (int d0 = 0; d0 < D_; d0 += 32) {
#pragma unroll
        for (int i = 0; i < 2; i++) {
            int idx = tid + 256*i;
            int s = idx >> 3, g = idx & 7;
            float4 v = *(const float4*)(x + (((size_t)b*S_) + s0 + s)*D_ + d0 + 4*g);
            xs[4*g+0][s] = v.x; xs[4*g+1][s] = v.y; xs[4*g+2][s] = v.z; xs[4*g+3][s] = v.w;
        }
#pragma unroll
        for (int i = 0; i < 4; i++) {
            int idx = tid + 256*i;
            int dd = idx >> 5, g = idx & 31;
            *(float4*)&scs[dd][4*g] = *(const float4*)(g_SC + (((size_t)b*D_) + d0 + dd)*R_ + 4*g);
        }
        __syncthreads();
#pragma unroll
        for (int dd = 0; dd < 32; dd++) {
            unsigned long long q[4];
#pragma unroll
            for (int i = 0; i < 4; i++) q[i] = pack_dup(xs[dd][ty + i]);
            float4 ka = *(float4*)&scs[dd][tx];
            float4 kb = *(float4*)&scs[dd][tx+4];
            unsigned long long k2[4];
            k2[0] = *(unsigned long long*)&ka.x;
            k2[1] = *(unsigned long long*)&ka.z;
            k2[2] = *(unsigned long long*)&kb.x;
            k2[3] = *(unsigned long long*)&kb.z;
#pragma unroll
            for (int i = 0; i < 4; i++)
#pragma unroll
                for (int j = 0; j < 4; j++)
                    acc[i][j] = ffma2(q[i], k2[j], acc[i][j]);
        }
        __syncthreads();
    }
#pragma unroll
    for (int i = 0; i < 4; i++) {
        int tok = b*S_ + s0 + ty + i;
#pragma unroll
        for (int j = 0; j < 4; j++) {
            float lo, hi;
            unpack2(acc[i][j], lo, hi);
            g_Q  [(size_t)tok*R_ + tx + 2*j    ] = lo;
            g_Q  [(size_t)tok*R_ + tx + 2*j + 1] = hi;
            g_Qbf[(size_t)tok*R_ + tx + 2*j    ] = __float2bfloat16(lo);
            g_Qbf[(size_t)tok*R_ + tx + 2*j + 1] = __float2bfloat16(hi);
        }
    }
}

// ---------------- K3: bf16 mma.sync scores, persistent A fragments in registers ----------------
__global__ void __launch_bounds__(256, 2) score_mma_kernel() {
    extern __shared__ char sm[];
    __nv_bfloat16 (*Qs)[QSTR] = (__nv_bfloat16(*)[QSTR])(sm + QS_OFF);
    float (*Ss)[SSTR]         = (float(*)[SSTR])(sm + SS_OFF);

    int tid  = threadIdx.x;
    int wid  = tid >> 5;
    int lane = tid & 31;
    int t8   = lane & 7;
    int tl   = lane >> 3;

    int wm = wid & 3;            // m quarter (32 tokens)
    int wn = wid >> 2;           // n half    (32 knowledge)

    int token0 = blockIdx.x * 128;
    int split  = blockIdx.y;
    int nbase0 = split * NSPL4;

    uint32_t smbase = smem_u32(sm);
    uint32_t qs_u32 = smbase + QS_OFF;
    uint32_t ks_u32 = smbase + KS_OFF;

    uint32_t boff[2];
#pragma unroll
    for (int bp = 0; bp < 2; bp++)
        boff[bp] = (uint32_t)((wn*32 + bp*16 + (tl >> 1)*8 + t8)*QSTR + (tl & 1)*8) * 2;

    // ---- preload Q tile (128 tokens x 128 bf16)
    {
        const uint4* src = (const uint4*)(g_Qbf + (size_t)token0 * R_);
#pragma unroll
        for (int i = 0; i < 8; i++) {
            int idx = tid + 256*i;
            int row = idx >> 4, c = idx & 15;
            *(uint4*)&Qs[row][c*8] = src[idx];
        }
    }
    // ---- preload first K chunk via cp.async
    {
        const uint4* src = (const uint4*)(g_Kbf + (size_t)nbase0 * R_);
#pragma unroll
        for (int i = 0; i < 4; i++) {
            int idx = tid + 256*i;
            int row = idx >> 4, c = idx & 15;
            cp_async16(ks_u32 + (uint32_t)(row*QSTR + c*8)*2, src + idx);
        }
        cp_commit();
    }

    // ---- load persistent A fragments (Q invariant across chunks): 64 regs
    __syncthreads();   // Q tile visible
    uint32_t A[2][8][4];
    {
#pragma unroll
        for (int mf = 0; mf < 2; mf++) {
            uint32_t abase = qs_u32 +
                (uint32_t)((wm*32 + mf*16 + (tl & 1)*8 + t8)*QSTR + (tl >> 1)*8) * 2;
#pragma unroll
            for (int ks = 0; ks < 8; ks++)
                ldsm_x4(A[mf][ks][0], A[mf][ks][1], A[mf][ks][2], A[mf][ks][3],
                        abase + (uint32_t)(ks*32));
        }
    }

    int tok  = tid & 127;
    int half = tid >> 7;

    float ts[NCAND]; int ti[NCAND];
#pragma unroll
    for (int k = 0; k < NCAND; k++) { ts[k] = -3.402823466e38f; ti[k] = 0; }

    for (int ch = 0; ch < NCH; ch++) {
        int p = ch & 1;
        cp_wait0();
        __syncthreads();   // K[p] arrived; previous scan of Ss done

        // ---- prefetch next K chunk into K[p^1]
        if (ch + 1 < NCH) {
            const uint4* src = (const uint4*)(g_Kbf + (size_t)(nbase0 + (ch+1)*CHN) * R_);
            uint32_t dst = ks_u32 + (uint32_t)(p ^ 1)*KSZ;
#pragma unroll
            for (int i = 0; i < 4; i++) {
                int idx = tid + 256*i;
                int row = idx >> 4, c = idx & 15;
                cp_async16(dst + (uint32_t)(row*QSTR + c*8)*2, src + idx);
            }
        }
        cp_commit();

        // ---- MMA phase: warp tile 32m x 32n, k=128 in 8 steps (B ldmatrix only)
        float c[2][4][4];
#pragma unroll
        for (int mf = 0; mf < 2; mf++)
#pragma unroll
            for (int nf = 0; nf < 4; nf++)
#pragma unroll
                for (int e = 0; e < 4; e++) c[mf][nf][e] = 0.f;

        uint32_t kbuf = ks_u32 + (uint32_t)p*KSZ;
#pragma unroll
        for (int ks = 0; ks < 8; ks++) {
            uint32_t kb = (uint32_t)(ks*16)*2;
            uint32_t b[2][4];
#pragma unroll
            for (int bp = 0; bp < 2; bp++)
                ldsm_x4(b[bp][0], b[bp][1], b[bp][2], b[bp][3], kbuf + boff[bp] + kb);
#pragma unroll
            for (int mf = 0; mf < 2; mf++) {
#pragma unroll
                for (int bp = 0; bp < 2; bp++) {
                    mma_bf16(c[mf][2*bp+0], A[mf][ks][0], A[mf][ks][1], A[mf][ks][2],
                             A[mf][ks][3], b[bp][0], b[bp][1]);
                    mma_bf16(c[mf][2*bp+1], A[mf][ks][0], A[mf][ks][1], A[mf][ks][2],
                             A[mf][ks][3], b[bp][2], b[bp][3]);
                }
            }
        }
        // ---- dump C fragments to score tile
        {
            int g = lane >> 2, tig = lane & 3;
#pragma unroll
            for (int mf = 0; mf < 2; mf++) {
#pragma unroll
                for (int nf = 0; nf < 4; nf++) {
                    int row = wm*32 + mf*16 + g;
                    int col = wn*32 + nf*8 + tig*2;
                    *(float2*)&Ss[row    ][col] = make_float2(c[mf][nf][0], c[mf][nf][1]);
                    *(float2*)&Ss[row + 8][col] = make_float2(c[mf][nf][2], c[mf][nf][3]);
                }
            }
        }
        __syncthreads();   // Ss ready

        // ---- all 256 threads scan: token = tid&127, cols half*32..half*32+31
        {
            int nb = nbase0 + ch*CHN + half*32;
            const float* srow = &Ss[tok][half*32];
#pragma unroll 4
            for (int n4 = 0; n4 < 8; n4++) {
                float4 v = *(const float4*)(srow + 4*n4);
                float vv[4] = {v.x, v.y, v.z, v.w};
#pragma unroll
                for (int u = 0; u < 4; u++) {
                    float s = vv[u];
                    if (s > ts[NCAND-1]) {
                        int ni = nb + 4*n4 + u;
#pragma unroll
                        for (int k = 0; k < NCAND; k++) {
                            if (s > ts[k]) {
                                float tv = ts[k]; ts[k] = s; s = tv;
                                int tn = ti[k]; ti[k] = ni; ni = tn;
                            }
                        }
                    }
                }
            }
        }
    }

    // ---- merge the two halves' top-8 lists
    __syncthreads();
    if (tid >= 128) {
#pragma unroll
        for (int k = 0; k < NCAND; k++) {
            Ss[tok][k] = ts[k];
            ((int*)&Ss[tok][16])[k] = ti[k];
        }
    }
    __syncthreads();
    if (tid < 128) {
#pragma unroll
        for (int k2 = 0; k2 < NCAND; k2++) {
            float s = Ss[tok][k2];
            int  ni = ((int*)&Ss[tok][16])[k2];
            if (s > ts[NCAND-1]) {
#pragma unroll
                for (int k = 0; k < NCAND; k++) {
                    if (s > ts[k]) {
                        float tv = ts[k]; ts[k] = s; s = tv;
                        int tn = ti[k]; ti[k] = ni; ni = tn;
                    }
                }
            }
        }
        int gtok = token0 + tok;
#pragma unroll
        for (int k = 0; k < NCAND; k++)
            g_ci[((size_t)gtok*NSPLIT4 + split)*NCAND + k] = ti[k];
    }
}

// ---------------- K4: fused exact fp32 rescore + softmax + V gather (one block per token) ----------------
__global__ void rescore_gather_kernel(const float* __restrict__ kK,
                                      const float4* __restrict__ V4,
                                      float* __restrict__ out, int out_size) {
    int t = blockIdx.x;
    __shared__ float qs[128];
    __shared__ float ws[TK_];
    __shared__ int   is[TK_];
    int tid = threadIdx.x;

    if (tid < 128) qs[tid] = g_Q[(size_t)t*R_ + tid];
    __syncthreads();

    if (tid < 32) {
        int lane = tid;
        int cand = g_ci[(size_t)t*32 + lane];
        const float4* kr = (const float4*)(kK + (size_t)cand*R_);
        float acc = 0.f;
#pragma unroll
        for (int r4 = 0; r4 < 32; r4++) {
            float4 k4 = kr[r4];
            const float* q4 = &qs[4*r4];
            acc = fmaf(q4[0], k4.x, acc);
            acc = fmaf(q4[1], k4.y, acc);
            acc = fmaf(q4[2], k4.z, acc);
            acc = fmaf(q4[3], k4.w, acc);
        }
        float v = acc; int id = cand;
        float selv[TK_]; int seli[TK_];
#pragma unroll
        for (int k = 0; k < TK_; k++) {
            float bv = v; int bi = id;
#pragma unroll
            for (int off = 16; off > 0; off >>= 1) {
                float ov = __shfl_xor_sync(0xffffffffu, bv, off);
                int   oi = __shfl_xor_sync(0xffffffffu, bi, off);
                if (ov > bv || (ov == bv && oi < bi)) { bv = ov; bi = oi; }
            }
            selv[k] = bv; seli[k] = bi;
            if (id == bi) v = -3.402823466e38f;
        }
        float sv0 = selv[0] * SCALE_;
        float e[TK_]; float sum = 0.f;
#pragma unroll
        for (int k = 0; k < TK_; k++) { e[k] = expf(selv[k]*SCALE_ - sv0); sum += e[k]; }

        const int NBSD = B_*S_*D_;
        bool extended = (out_size >= NBSD + 2*NTOK*TK_);
        if (lane < TK_) {
            float w = e[lane] / sum;
            ws[lane] = w;
            is[lane] = seli[lane];
            if (extended) {
                out[NBSD + (size_t)t*TK_ + lane]            = (float)seli[lane];
                out[NBSD + NTOK*TK_ + (size_t)t*TK_ + lane] = w;
            }
        }
    }
    __syncthreads();

    int d4 = tid;                 // 0..255
    float4 acc = make_float4(0.f, 0.f, 0.f, 0.f);
#pragma unroll
    for (int k = 0; k < TK_; k++) {
        float w  = ws[k];
        float4 v = V4[(size_t)is[k]*(D_/4) + d4];
        acc.x = fmaf(w, v.x, acc.x);
        acc.y = fmaf(w, v.y, acc.y);
        acc.z = fmaf(w, v.z, acc.z);
        acc.w = fmaf(w, v.w, acc.w);
    }
    ((float4*)out)[(size_t)t*(D_/4) + d4] = acc;
}

// ---------------- launch ----------------
extern "C" void kernel_launch(void* const* d_in, const int* in_sizes, int n_in,
                              void* d_out, int out_size) {
    const float* x  = (const float*)d_in[0];
    const float* mw = (const float*)d_in[1];
    const float* cn = (const float*)d_in[2];
    const float* kK = (const float*)d_in[3];
    const float* kV = (const float*)d_in[4];
    float* out = (float*)d_out;

    cudaFuncSetAttribute(score_mma_kernel, cudaFuncAttributeMaxDynamicSharedMemorySize, SMEM_SC);

    sc_kernel<<<dim3(B_, D_), R_>>>(mw, cn);
    kbf_kernel<<<(NK_*R_/4)/256, 256>>>((const float4*)kK);
    q_kernel<<<dim3(S_/64, B_), 256>>>(x);
    score_mma_kernel<<<dim3(NTOK/128, NSPLIT4), 256, SMEM_SC>>>();
    rescore_gather_kernel<<<NTOK, 256>>>(kK, (const float4*)kV, out, out_size);
}

// round 15
// speedup vs baseline: 1.0486x; 1.0064x over previous
#include <cuda_runtime.h>
#include <cuda_bf16.h>
#include <cstdint>

// Problem constants
#define B_   4
#define S_   2048
#define D_   1024
#define NC_  16
#define NK_  32768
#define R_   128
#define TK_  8
#define NTOK (B_*S_)          // 8192 tokens
#define NSPLIT4 4
#define NSPL4 (NK_/NSPLIT4)   // 8192 knowledge rows per split
#define CHN  64               // knowledge rows per chunk
#define NCH  (NSPL4/CHN)      // 128 chunks
#define NCAND 8               // top-8 per split -> 32 candidates/token

#define SCALE_ 0.08838834764831845f

#define QSTR 136              // bf16 smem row stride (Q/K tiles)
#define SSTR 68               // fp32 smem row stride (score tile)

// smem offsets (bytes)
#define QS_OFF 0
#define KS_OFF (128*QSTR*2)              // 34816
#define KSZ    (64*QSTR*2)               // 17408 per K buffer
#define SS_OFF (KS_OFF + 2*KSZ)          // 69632
#define SMEM_SC (SS_OFF + 128*SSTR*4)    // 104448  -> 2 CTAs/SM

// ---------------- scratch ----------------
__device__ float          g_SC [B_*D_*R_];
__device__ float          g_Q  [NTOK*R_];
__device__ __nv_bfloat16  g_Qbf[NTOK*R_];
__device__ __nv_bfloat16  g_Kbf[NK_*R_];
__device__ int            g_ci [NTOK*NSPLIT4*NCAND];

// ---------------- PTX helpers ----------------
__device__ __forceinline__ uint32_t smem_u32(const void* p) {
    uint32_t a;
    asm("{ .reg .u64 t; cvta.to.shared.u64 t, %1; cvt.u32.u64 %0, t; }" : "=r"(a) : "l"(p));
    return a;
}
__device__ __forceinline__ void ldsm_x4(uint32_t& r0, uint32_t& r1, uint32_t& r2, uint32_t& r3,
                                        uint32_t addr) {
    asm volatile("ldmatrix.sync.aligned.m8n8.x4.shared.b16 {%0,%1,%2,%3}, [%4];"
                 : "=r"(r0), "=r"(r1), "=r"(r2), "=r"(r3) : "r"(addr));
}
__device__ __forceinline__ void cp_async16(uint32_t saddr, const void* gptr) {
    asm volatile("cp.async.cg.shared.global [%0], [%1], 16;" :: "r"(saddr), "l"(gptr));
}
__device__ __forceinline__ void cp_commit() { asm volatile("cp.async.commit_group;"); }
__device__ __forceinline__ void cp_wait0()  { asm volatile("cp.async.wait_group 0;" ::: "memory"); }

__device__ __forceinline__ void mma_bf16(float c[4], uint32_t a0, uint32_t a1, uint32_t a2,
                                         uint32_t a3, uint32_t b0, uint32_t b1) {
    asm volatile(
        "mma.sync.aligned.m16n8k16.row.col.f32.bf16.bf16.f32 "
        "{%0,%1,%2,%3}, {%4,%5,%6,%7}, {%8,%9}, {%0,%1,%2,%3};"
        : "+f"(c[0]), "+f"(c[1]), "+f"(c[2]), "+f"(c[3])
        : "r"(a0), "r"(a1), "r"(a2), "r"(a3), "r"(b0), "r"(b1));
}

// packed fp32x2 FMA (exact per-lane fp32 rounding)
__device__ __forceinline__ unsigned long long ffma2(unsigned long long a,
                                                    unsigned long long b,
                                                    unsigned long long c) {
    unsigned long long d;
    asm("fma.rn.f32x2 %0, %1, %2, %3;" : "=l"(d) : "l"(a), "l"(b), "l"(c));
    return d;
}
__device__ __forceinline__ unsigned long long pack_dup(float v) {
    unsigned long long d;
    asm("mov.b64 %0, {%1, %2};" : "=l"(d) : "f"(v), "f"(v));
    return d;
}
__device__ __forceinline__ void unpack2(unsigned long long d, float& lo, float& hi) {
    asm("mov.b64 {%0, %1}, %2;" : "=f"(lo), "=f"(hi) : "l"(d));
}

// ---------------- K1: shared_compress + fused K->bf16 conversion ----------------
__global__ void sc_kernel(const float* __restrict__ mw, const float* __restrict__ cn,
                          const float4* __restrict__ kK) {
    int b = blockIdx.x, d = blockIdx.y, r = threadIdx.x;

    // fused kbf work: this block's share of K conversion (2 float4 per thread)
    // global thread id over 4096 blocks x 128 threads = 524288; K = 1048576 float4
    {
        int gt = (blockIdx.x * gridDim.y + blockIdx.y) * 128 + threadIdx.x;
#pragma unroll
        for (int u = 0; u < 2; u++) {
            int i = gt + u * 524288;
            float4 v = kK[i];
            __nv_bfloat16* dst = g_Kbf + (size_t)i * 4;
            dst[0] = __float2bfloat16(v.x); dst[1] = __float2bfloat16(v.y);
            dst[2] = __float2bfloat16(v.z); dst[3] = __float2bfloat16(v.w);
        }
    }

    float acc = 0.f;
#pragma unroll
    for (int n = 0; n < NC_; n++)
        acc = fmaf(mw[b*NC_ + n], cn[((size_t)n*D_ + d)*R_ + r], acc);
    g_SC[((size_t)b*D_ + d)*R_ + r] = acc;
}

// ---------------- K2: Q projection (fp32 exact, d-ascending chain, packed FFMA2) ----------------
__global__ void q_kernel(const float* __restrict__ x) {
    __shared__ float xs[32][68];
    __shared__ float scs[32][128];
    int tid = threadIdx.x;
    int b = blockIdx.y, s0 = blockIdx.x*64;

    unsigned long long acc[4][4];
#pragma unroll
    for (int i = 0; i < 4; i++)
#pragma unroll
        for (int j = 0; j < 4; j++) acc[i][j] = 0ull;

    int tx = (tid & 15)*8;
    int ty = (tid >> 4)*4;

    for (int d0 = 0; d0 < D_; d0 += 32) {
#pragma unroll
        for (int i = 0; i < 2; i++) {
            int idx = tid + 256*i;
            int s = idx >> 3, g = idx & 7;
            float4 v = *(const float4*)(x + (((size_t)b*S_) + s0 + s)*D_ + d0 + 4*g);
            xs[4*g+0][s] = v.x; xs[4*g+1][s] = v.y; xs[4*g+2][s] = v.z; xs[4*g+3][s] = v.w;
        }
#pragma unroll
        for (int i = 0; i < 4; i++) {
            int idx = tid + 256*i;
            int dd = idx >> 5, g = idx & 31;
            *(float4*)&scs[dd][4*g] = *(const float4*)(g_SC + (((size_t)b*D_) + d0 + dd)*R_ + 4*g);
        }
        __syncthreads();
#pragma unroll
        for (int dd = 0; dd < 32; dd++) {
            unsigned long long q[4];
#pragma unroll
            for (int i = 0; i < 4; i++) q[i] = pack_dup(xs[dd][ty + i]);
            float4 ka = *(float4*)&scs[dd][tx];
            float4 kb = *(float4*)&scs[dd][tx+4];
            unsigned long long k2[4];
            k2[0] = *(unsigned long long*)&ka.x;
            k2[1] = *(unsigned long long*)&ka.z;
            k2[2] = *(unsigned long long*)&kb.x;
            k2[3] = *(unsigned long long*)&kb.z;
#pragma unroll
            for (int i = 0; i < 4; i++)
#pragma unroll
                for (int j = 0; j < 4; j++)
                    acc[i][j] = ffma2(q[i], k2[j], acc[i][j]);
        }
        __syncthreads();
    }
#pragma unroll
    for (int i = 0; i < 4; i++) {
        int tok = b*S_ + s0 + ty + i;
#pragma unroll
        for (int j = 0; j < 4; j++) {
            float lo, hi;
            unpack2(acc[i][j], lo, hi);
            g_Q  [(size_t)tok*R_ + tx + 2*j    ] = lo;
            g_Q  [(size_t)tok*R_ + tx + 2*j + 1] = hi;
            g_Qbf[(size_t)tok*R_ + tx + 2*j    ] = __float2bfloat16(lo);
            g_Qbf[(size_t)tok*R_ + tx + 2*j + 1] = __float2bfloat16(hi);
        }
    }
}

// ---------------- K3: bf16 mma.sync scores, persistent A fragments in registers ----------------
__global__ void __launch_bounds__(256, 2) score_mma_kernel() {
    extern __shared__ char sm[];
    __nv_bfloat16 (*Qs)[QSTR] = (__nv_bfloat16(*)[QSTR])(sm + QS_OFF);
    float (*Ss)[SSTR]         = (float(*)[SSTR])(sm + SS_OFF);

    int tid  = threadIdx.x;
    int wid  = tid >> 5;
    int lane = tid & 31;
    int t8   = lane & 7;
    int tl   = lane >> 3;

    int wm = wid & 3;            // m quarter (32 tokens)
    int wn = wid >> 2;           // n half    (32 knowledge)

    int token0 = blockIdx.x * 128;
    int split  = blockIdx.y;
    int nbase0 = split * NSPL4;

    uint32_t smbase = smem_u32(sm);
    uint32_t qs_u32 = smbase + QS_OFF;
    uint32_t ks_u32 = smbase + KS_OFF;

    uint32_t boff[2];
#pragma unroll
    for (int bp = 0; bp < 2; bp++)
        boff[bp] = (uint32_t)((wn*32 + bp*16 + (tl >> 1)*8 + t8)*QSTR + (tl & 1)*8) * 2;

    // ---- preload Q tile (128 tokens x 128 bf16)
    {
        const uint4* src = (const uint4*)(g_Qbf + (size_t)token0 * R_);
#pragma unroll
        for (int i = 0; i < 8; i++) {
            int idx = tid + 256*i;
            int row = idx >> 4, c = idx & 15;
            *(uint4*)&Qs[row][c*8] = src[idx];
        }
    }
    // ---- preload first K chunk via cp.async
    {
        const uint4* src = (const uint4*)(g_Kbf + (size_t)nbase0 * R_);
#pragma unroll
        for (int i = 0; i < 4; i++) {
            int idx = tid + 256*i;
            int row = idx >> 4, c = idx & 15;
            cp_async16(ks_u32 + (uint32_t)(row*QSTR + c*8)*2, src + idx);
        }
        cp_commit();
    }

    // ---- load persistent A fragments (Q invariant across chunks): 64 regs
    __syncthreads();   // Q tile visible
    uint32_t A[2][8][4];
    {
#pragma unroll
        for (int mf = 0; mf < 2; mf++) {
            uint32_t abase = qs_u32 +
                (uint32_t)((wm*32 + mf*16 + (tl & 1)*8 + t8)*QSTR + (tl >> 1)*8) * 2;
#pragma unroll
            for (int ks = 0; ks < 8; ks++)
                ldsm_x4(A[mf][ks][0], A[mf][ks][1], A[mf][ks][2], A[mf][ks][3],
                        abase + (uint32_t)(ks*32));
        }
    }

    int tok  = tid & 127;
    int half = tid >> 7;

    float ts[NCAND]; int ti[NCAND];
#pragma unroll
    for (int k = 0; k < NCAND; k++) { ts[k] = -3.402823466e38f; ti[k] = 0; }

    for (int ch = 0; ch < NCH; ch++) {
        int p = ch & 1;
        cp_wait0();
        __syncthreads();   // K[p] arrived; previous scan of Ss done

        // ---- prefetch next K chunk into K[p^1]
        if (ch + 1 < NCH) {
            const uint4* src = (const uint4*)(g_Kbf + (size_t)(nbase0 + (ch+1)*CHN) * R_);
            uint32_t dst = ks_u32 + (uint32_t)(p ^ 1)*KSZ;
#pragma unroll
            for (int i = 0; i < 4; i++) {
                int idx = tid + 256*i;
                int row = idx >> 4, c = idx & 15;
                cp_async16(dst + (uint32_t)(row*QSTR + c*8)*2, src + idx);
            }
        }
        cp_commit();

        // ---- MMA phase: warp tile 32m x 32n, k=128 in 8 steps (B ldmatrix only)
        float c[2][4][4];
#pragma unroll
        for (int mf = 0; mf < 2; mf++)
#pragma unroll
            for (int nf = 0; nf < 4; nf++)
#pragma unroll
                for (int e = 0; e < 4; e++) c[mf][nf][e] = 0.f;

        uint32_t kbuf = ks_u32 + (uint32_t)p*KSZ;
#pragma unroll
        for (int ks = 0; ks < 8; ks++) {
            uint32_t kb = (uint32_t)(ks*16)*2;
            uint32_t b[2][4];
#pragma unroll
            for (int bp = 0; bp < 2; bp++)
                ldsm_x4(b[bp][0], b[bp][1], b[bp][2], b[bp][3], kbuf + boff[bp] + kb);
#pragma unroll
            for (int mf = 0; mf < 2; mf++) {
#pragma unroll
                for (int bp = 0; bp < 2; bp++) {
                    mma_bf16(c[mf][2*bp+0], A[mf][ks][0], A[mf][ks][1], A[mf][ks][2],
                             A[mf][ks][3], b[bp][0], b[bp][1]);
                    mma_bf16(c[mf][2*bp+1], A[mf][ks][0], A[mf][ks][1], A[mf][ks][2],
                             A[mf][ks][3], b[bp][2], b[bp][3]);
                }
            }
        }
        // ---- dump C fragments to score tile
        {
            int g = lane >> 2, tig = lane & 3;
#pragma unroll
            for (int mf = 0; mf < 2; mf++) {
#pragma unroll
                for (int nf = 0; nf < 4; nf++) {
                    int row = wm*32 + mf*16 + g;
                    int col = wn*32 + nf*8 + tig*2;
                    *(float2*)&Ss[row    ][col] = make_float2(c[mf][nf][0], c[mf][nf][1]);
                    *(float2*)&Ss[row + 8][col] = make_float2(c[mf][nf][2], c[mf][nf][3]);
                }
            }
        }
        __syncthreads();   // Ss ready

        // ---- all 256 threads scan: token = tid&127, cols half*32..half*32+31
        {
            int nb = nbase0 + ch*CHN + half*32;
            const float* srow = &Ss[tok][half*32];
#pragma unroll 4
            for (int n4 = 0; n4 < 8; n4++) {
                float4 v = *(const float4*)(srow + 4*n4);
                float vv[4] = {v.x, v.y, v.z, v.w};
#pragma unroll
                for (int u = 0; u < 4; u++) {
                    float s = vv[u];
                    if (s > ts[NCAND-1]) {
                        int ni = nb + 4*n4 + u;
#pragma unroll
                        for (int k = 0; k < NCAND; k++) {
                            if (s > ts[k]) {
                                float tv = ts[k]; ts[k] = s; s = tv;
                                int tn = ti[k]; ti[k] = ni; ni = tn;
                            }
                        }
                    }
                }
            }
        }
    }

    // ---- merge the two halves' top-8 lists
    __syncthreads();
    if (tid >= 128) {
#pragma unroll
        for (int k = 0; k < NCAND; k++) {
            Ss[tok][k] = ts[k];
            ((int*)&Ss[tok][16])[k] = ti[k];
        }
    }
    __syncthreads();
    if (tid < 128) {
#pragma unroll
        for (int k2 = 0; k2 < NCAND; k2++) {
            float s = Ss[tok][k2];
            int  ni = ((int*)&Ss[tok][16])[k2];
            if (s > ts[NCAND-1]) {
#pragma unroll
                for (int k = 0; k < NCAND; k++) {
                    if (s > ts[k]) {
                        float tv = ts[k]; ts[k] = s; s = tv;
                        int tn = ti[k]; ti[k] = ni; ni = tn;
                    }
                }
            }
        }
        int gtok = token0 + tok;
#pragma unroll
        for (int k = 0; k < NCAND; k++)
            g_ci[((size_t)gtok*NSPLIT4 + split)*NCAND + k] = ti[k];
    }
}

// ---------------- K4: fused exact fp32 rescore + softmax + V gather (one block per token) ----------------
__global__ void rescore_gather_kernel(const float* __restrict__ kK,
                                      const float4* __restrict__ V4,
                                      float* __restrict__ out, int out_size) {
    int t = blockIdx.x;
    __shared__ float qs[128];
    __shared__ float ws[TK_];
    __shared__ int   is[TK_];
    int tid = threadIdx.x;

    if (tid < 128) qs[tid] = g_Q[(size_t)t*R_ + tid];
    __syncthreads();

    if (tid < 32) {
        int lane = tid;
        int cand = g_ci[(size_t)t*32 + lane];
        const float4* kr = (const float4*)(kK + (size_t)cand*R_);
        float acc = 0.f;
#pragma unroll
        for (int r4 = 0; r4 < 32; r4++) {
            float4 k4 = kr[r4];
            const float* q4 = &qs[4*r4];
            acc = fmaf(q4[0], k4.x, acc);
            acc = fmaf(q4[1], k4.y, acc);
            acc = fmaf(q4[2], k4.z, acc);
            acc = fmaf(q4[3], k4.w, acc);
        }
        float v = acc; int id = cand;
        float selv[TK_]; int seli[TK_];
#pragma unroll
        for (int k = 0; k < TK_; k++) {
            float bv = v; int bi = id;
#pragma unroll
            for (int off = 16; off > 0; off >>= 1) {
                float ov = __shfl_xor_sync(0xffffffffu, bv, off);
                int   oi = __shfl_xor_sync(0xffffffffu, bi, off);
                if (ov > bv || (ov == bv && oi < bi)) { bv = ov; bi = oi; }
            }
            selv[k] = bv; seli[k] = bi;
            if (id == bi) v = -3.402823466e38f;
        }
        float sv0 = selv[0] * SCALE_;
        float e[TK_]; float sum = 0.f;
#pragma unroll
        for (int k = 0; k < TK_; k++) { e[k] = expf(selv[k]*SCALE_ - sv0); sum += e[k]; }

        const int NBSD = B_*S_*D_;
        bool extended = (out_size >= NBSD + 2*NTOK*TK_);
        if (lane < TK_) {
            float w = e[lane] / sum;
            ws[lane] = w;
            is[lane] = seli[lane];
            if (extended) {
                out[NBSD + (size_t)t*TK_ + lane]            = (float)seli[lane];
                out[NBSD + NTOK*TK_ + (size_t)t*TK_ + lane] = w;
            }
        }
    }
    __syncthreads();

    int d4 = tid;                 // 0..255
    float4 acc = make_float4(0.f, 0.f, 0.f, 0.f);
#pragma unroll
    for (int k = 0; k < TK_; k++) {
        float w  = ws[k];
        float4 v = V4[(size_t)is[k]*(D_/4) + d4];
        acc.x = fmaf(w, v.x, acc.x);
        acc.y = fmaf(w, v.y, acc.y);
        acc.z = fmaf(w, v.z, acc.z);
        acc.w = fmaf(w, v.w, acc.w);
    }
    ((float4*)out)[(size_t)t*(D_/4) + d4] = acc;
}

// ---------------- launch ----------------
extern "C" void kernel_launch(void* const* d_in, const int* in_sizes, int n_in,
                              void* d_out, int out_size) {
    const float* x  = (const float*)d_in[0];
    const float* mw = (const float*)d_in[1];
    const float* cn = (const float*)d_in[2];
    const float* kK = (const float*)d_in[3];
    const float* kV = (const float*)d_in[4];
    float* out = (float*)d_out;

    cudaFuncSetAttribute(score_mma_kernel, cudaFuncAttributeMaxDynamicSharedMemorySize, SMEM_SC);

    sc_kernel<<<dim3(B_, D_), R_>>>(mw, cn, (const float4*)kK);
    q_kernel<<<dim3(S_/64, B_), 256>>>(x);
    score_mma_kernel<<<dim3(NTOK/128, NSPLIT4), 256, SMEM_SC>>>();
    rescore_gather_kernel<<<NTOK, 256>>>(kK, (const float4*)kV, out, out_size);
}

// round 16
// speedup vs baseline: 1.0572x; 1.0082x over previous
#include <cuda_runtime.h>
#include <cuda_bf16.h>
#include <cstdint>

// Problem constants
#define B_   4
#define S_   2048
#define D_   1024
#define NC_  16
#define NK_  32768
#define R_   128
#define TK_  8
#define NTOK (B_*S_)          // 8192 tokens
#define NSPLIT4 4
#define NSPL4 (NK_/NSPLIT4)   // 8192 knowledge rows per split
#define CHN  64               // knowledge rows per chunk
#define NCH  (NSPL4/CHN)      // 128 chunks
#define NCAND 8               // top-8 per split -> 32 candidates/token

#define SCALE_ 0.08838834764831845f

#define QSTR 136              // bf16 smem row stride (Q/K tiles)
#define SSTR 68               // fp32 smem row stride (score tile)

// smem offsets (bytes)
#define QS_OFF 0
#define KS_OFF (128*QSTR*2)              // 34816
#define KSZ    (64*QSTR*2)               // 17408 per K buffer
#define SS_OFF (KS_OFF + 2*KSZ)          // 69632
#define SMEM_SC (SS_OFF + 128*SSTR*4)    // 104448  -> 2 CTAs/SM

// ---------------- scratch ----------------
__device__ float          g_SC [B_*D_*R_];
__device__ float          g_Q  [NTOK*R_];
__device__ __nv_bfloat16  g_Qbf[NTOK*R_];
__device__ __nv_bfloat16  g_Kbf[NK_*R_];
__device__ int            g_ci [NTOK*NSPLIT4*NCAND];

// ---------------- PTX helpers ----------------
__device__ __forceinline__ uint32_t smem_u32(const void* p) {
    uint32_t a;
    asm("{ .reg .u64 t; cvta.to.shared.u64 t, %1; cvt.u32.u64 %0, t; }" : "=r"(a) : "l"(p));
    return a;
}
__device__ __forceinline__ void ldsm_x4(uint32_t& r0, uint32_t& r1, uint32_t& r2, uint32_t& r3,
                                        uint32_t addr) {
    asm volatile("ldmatrix.sync.aligned.m8n8.x4.shared.b16 {%0,%1,%2,%3}, [%4];"
                 : "=r"(r0), "=r"(r1), "=r"(r2), "=r"(r3) : "r"(addr));
}
__device__ __forceinline__ void cp_async16(uint32_t saddr, const void* gptr) {
    asm volatile("cp.async.cg.shared.global [%0], [%1], 16;" :: "r"(saddr), "l"(gptr));
}
__device__ __forceinline__ void cp_commit() { asm volatile("cp.async.commit_group;"); }
__device__ __forceinline__ void cp_wait0()  { asm volatile("cp.async.wait_group 0;" ::: "memory"); }

__device__ __forceinline__ void mma_bf16(float c[4], uint32_t a0, uint32_t a1, uint32_t a2,
                                         uint32_t a3, uint32_t b0, uint32_t b1) {
    asm volatile(
        "mma.sync.aligned.m16n8k16.row.col.f32.bf16.bf16.f32 "
        "{%0,%1,%2,%3}, {%4,%5,%6,%7}, {%8,%9}, {%0,%1,%2,%3};"
        : "+f"(c[0]), "+f"(c[1]), "+f"(c[2]), "+f"(c[3])
        : "r"(a0), "r"(a1), "r"(a2), "r"(a3), "r"(b0), "r"(b1));
}

// packed fp32x2 FMA (exact per-lane fp32 rounding)
__device__ __forceinline__ unsigned long long ffma2(unsigned long long a,
                                                    unsigned long long b,
                                                    unsigned long long c) {
    unsigned long long d;
    asm("fma.rn.f32x2 %0, %1, %2, %3;" : "=l"(d) : "l"(a), "l"(b), "l"(c));
    return d;
}
__device__ __forceinline__ unsigned long long pack_dup(float v) {
    unsigned long long d;
    asm("mov.b64 %0, {%1, %2};" : "=l"(d) : "f"(v), "f"(v));
    return d;
}
__device__ __forceinline__ void unpack2(unsigned long long d, float& lo, float& hi) {
    asm("mov.b64 {%0, %1}, %2;" : "=f"(lo), "=f"(hi) : "l"(d));
}

// ---------------- K1: shared_compress + fused K->bf16 conversion ----------------
__global__ void sc_kernel(const float* __restrict__ mw, const float* __restrict__ cn,
                          const float4* __restrict__ kK) {
    int b = blockIdx.x, d = blockIdx.y, r = threadIdx.x;

    // fused kbf work: this block's share of K conversion (2 float4 per thread)
    {
        int gt = (blockIdx.x * gridDim.y + blockIdx.y) * 128 + threadIdx.x;
#pragma unroll
        for (int u = 0; u < 2; u++) {
            int i = gt + u * 524288;
            float4 v = kK[i];
            __nv_bfloat16* dst = g_Kbf + (size_t)i * 4;
            dst[0] = __float2bfloat16(v.x); dst[1] = __float2bfloat16(v.y);
            dst[2] = __float2bfloat16(v.z); dst[3] = __float2bfloat16(v.w);
        }
    }

    float acc = 0.f;
#pragma unroll
    for (int n = 0; n < NC_; n++)
        acc = fmaf(mw[b*NC_ + n], cn[((size_t)n*D_ + d)*R_ + r], acc);
    g_SC[((size_t)b*D_ + d)*R_ + r] = acc;
}

// ---------------- K2: Q projection (fp32 exact, d-ascending chain, packed FFMA2) ----------------
__global__ void q_kernel(const float* __restrict__ x) {
    __shared__ float xs[32][68];
    __shared__ float scs[32][128];
    int tid = threadIdx.x;
    int b = blockIdx.y, s0 = blockIdx.x*64;

    unsigned long long acc[4][4];
#pragma unroll
    for (int i = 0; i < 4; i++)
#pragma unroll
        for (int j = 0; j < 4; j++) acc[i][j] = 0ull;

    int tx = (tid & 15)*8;
    int ty = (tid >> 4)*4;

    for (int d0 = 0; d0 < D_; d0 += 32) {
#pragma unroll
        for (int i = 0; i < 2; i++) {
            int idx = tid + 256*i;
            int s = idx >> 3, g = idx & 7;
            float4 v = *(const float4*)(x + (((size_t)b*S_) + s0 + s)*D_ + d0 + 4*g);
            xs[4*g+0][s] = v.x; xs[4*g+1][s] = v.y; xs[4*g+2][s] = v.z; xs[4*g+3][s] = v.w;
        }
#pragma unroll
        for (int i = 0; i < 4; i++) {
            int idx = tid + 256*i;
            int dd = idx >> 5, g = idx & 31;
            *(float4*)&scs[dd][4*g] = *(const float4*)(g_SC + (((size_t)b*D_) + d0 + dd)*R_ + 4*g);
        }
        __syncthreads();
#pragma unroll
        for (int dd = 0; dd < 32; dd++) {
            // one LDS.128 for 4 q values (xs row stride 272B and ty*4B are 16B-aligned)
            float4 qv = *(const float4*)&xs[dd][ty];
            unsigned long long q[4];
            q[0] = pack_dup(qv.x); q[1] = pack_dup(qv.y);
            q[2] = pack_dup(qv.z); q[3] = pack_dup(qv.w);
            float4 ka = *(float4*)&scs[dd][tx];
            float4 kb = *(float4*)&scs[dd][tx+4];
            unsigned long long k2[4];
            k2[0] = *(unsigned long long*)&ka.x;
            k2[1] = *(unsigned long long*)&ka.z;
            k2[2] = *(unsigned long long*)&kb.x;
            k2[3] = *(unsigned long long*)&kb.z;
#pragma unroll
            for (int i = 0; i < 4; i++)
#pragma unroll
                for (int j = 0; j < 4; j++)
                    acc[i][j] = ffma2(q[i], k2[j], acc[i][j]);
        }
        __syncthreads();
    }
#pragma unroll
    for (int i = 0; i < 4; i++) {
        int tok = b*S_ + s0 + ty + i;
#pragma unroll
        for (int j = 0; j < 4; j++) {
            float lo, hi;
            unpack2(acc[i][j], lo, hi);
            g_Q  [(size_t)tok*R_ + tx + 2*j    ] = lo;
            g_Q  [(size_t)tok*R_ + tx + 2*j + 1] = hi;
            g_Qbf[(size_t)tok*R_ + tx + 2*j    ] = __float2bfloat16(lo);
            g_Qbf[(size_t)tok*R_ + tx + 2*j + 1] = __float2bfloat16(hi);
        }
    }
}

// ---------------- K3: bf16 mma.sync scores, persistent A fragments in registers ----------------
__global__ void __launch_bounds__(256, 2) score_mma_kernel() {
    extern __shared__ char sm[];
    __nv_bfloat16 (*Qs)[QSTR] = (__nv_bfloat16(*)[QSTR])(sm + QS_OFF);
    float (*Ss)[SSTR]         = (float(*)[SSTR])(sm + SS_OFF);

    int tid  = threadIdx.x;
    int wid  = tid >> 5;
    int lane = tid & 31;
    int t8   = lane & 7;
    int tl   = lane >> 3;

    int wm = wid & 3;            // m quarter (32 tokens)
    int wn = wid >> 2;           // n half    (32 knowledge)

    int token0 = blockIdx.x * 128;
    int split  = blockIdx.y;
    int nbase0 = split * NSPL4;

    uint32_t smbase = smem_u32(sm);
    uint32_t qs_u32 = smbase + QS_OFF;
    uint32_t ks_u32 = smbase + KS_OFF;

    uint32_t boff[2];
#pragma unroll
    for (int bp = 0; bp < 2; bp++)
        boff[bp] = (uint32_t)((wn*32 + bp*16 + (tl >> 1)*8 + t8)*QSTR + (tl & 1)*8) * 2;

    // ---- preload Q tile (128 tokens x 128 bf16)
    {
        const uint4* src = (const uint4*)(g_Qbf + (size_t)token0 * R_);
#pragma unroll
        for (int i = 0; i < 8; i++) {
            int idx = tid + 256*i;
            int row = idx >> 4, c = idx & 15;
            *(uint4*)&Qs[row][c*8] = src[idx];
        }
    }
    // ---- preload first K chunk via cp.async
    {
        const uint4* src = (const uint4*)(g_Kbf + (size_t)nbase0 * R_);
#pragma unroll
        for (int i = 0; i < 4; i++) {
            int idx = tid + 256*i;
            int row = idx >> 4, c = idx & 15;
            cp_async16(ks_u32 + (uint32_t)(row*QSTR + c*8)*2, src + idx);
        }
        cp_commit();
    }

    // ---- load persistent A fragments (Q invariant across chunks): 64 regs
    __syncthreads();   // Q tile visible
    uint32_t A[2][8][4];
    {
#pragma unroll
        for (int mf = 0; mf < 2; mf++) {
            uint32_t abase = qs_u32 +
                (uint32_t)((wm*32 + mf*16 + (tl & 1)*8 + t8)*QSTR + (tl >> 1)*8) * 2;
#pragma unroll
            for (int ks = 0; ks < 8; ks++)
                ldsm_x4(A[mf][ks][0], A[mf][ks][1], A[mf][ks][2], A[mf][ks][3],
                        abase + (uint32_t)(ks*32));
        }
    }

    int tok  = tid & 127;
    int half = tid >> 7;

    float ts[NCAND]; int ti[NCAND];
#pragma unroll
    for (int k = 0; k < NCAND; k++) { ts[k] = -3.402823466e38f; ti[k] = 0; }

    for (int ch = 0; ch < NCH; ch++) {
        int p = ch & 1;
        cp_wait0();
        __syncthreads();   // K[p] arrived; previous scan of Ss done

        // ---- prefetch next K chunk into K[p^1]
        if (ch + 1 < NCH) {
            const uint4* src = (const uint4*)(g_Kbf + (size_t)(nbase0 + (ch+1)*CHN) * R_);
            uint32_t dst = ks_u32 + (uint32_t)(p ^ 1)*KSZ;
#pragma unroll
            for (int i = 0; i < 4; i++) {
                int idx = tid + 256*i;
                int row = idx >> 4, c = idx & 15;
                cp_async16(dst + (uint32_t)(row*QSTR + c*8)*2, src + idx);
            }
        }
        cp_commit();

        // ---- MMA phase: warp tile 32m x 32n, k=128 in 8 steps (B ldmatrix only)
        float c[2][4][4];
#pragma unroll
        for (int mf = 0; mf < 2; mf++)
#pragma unroll
            for (int nf = 0; nf < 4; nf++)
#pragma unroll
                for (int e = 0; e < 4; e++) c[mf][nf][e] = 0.f;

        uint32_t kbuf = ks_u32 + (uint32_t)p*KSZ;
#pragma unroll
        for (int ks = 0; ks < 8; ks++) {
            uint32_t kb = (uint32_t)(ks*16)*2;
            uint32_t b[2][4];
#pragma unroll
            for (int bp = 0; bp < 2; bp++)
                ldsm_x4(b[bp][0], b[bp][1], b[bp][2], b[bp][3], kbuf + boff[bp] + kb);
#pragma unroll
            for (int mf = 0; mf < 2; mf++) {
#pragma unroll
                for (int bp = 0; bp < 2; bp++) {
                    mma_bf16(c[mf][2*bp+0], A[mf][ks][0], A[mf][ks][1], A[mf][ks][2],
                             A[mf][ks][3], b[bp][0], b[bp][1]);
                    mma_bf16(c[mf][2*bp+1], A[mf][ks][0], A[mf][ks][1], A[mf][ks][2],
                             A[mf][ks][3], b[bp][2], b[bp][3]);
                }
            }
        }
        // ---- dump C fragments to score tile
        {
            int g = lane >> 2, tig = lane & 3;
#pragma unroll
            for (int mf = 0; mf < 2; mf++) {
#pragma unroll
                for (int nf = 0; nf < 4; nf++) {
                    int row = wm*32 + mf*16 + g;
                    int col = wn*32 + nf*8 + tig*2;
                    *(float2*)&Ss[row    ][col] = make_float2(c[mf][nf][0], c[mf][nf][1]);
                    *(float2*)&Ss[row + 8][col] = make_float2(c[mf][nf][2], c[mf][nf][3]);
                }
            }
        }
        __syncthreads();   // Ss ready

        // ---- all 256 threads scan: token = tid&127, cols half*32..half*32+31
        {
            int nb = nbase0 + ch*CHN + half*32;
            const float* srow = &Ss[tok][half*32];
#pragma unroll 4
            for (int n4 = 0; n4 < 8; n4++) {
                float4 v = *(const float4*)(srow + 4*n4);
                float vv[4] = {v.x, v.y, v.z, v.w};
#pragma unroll
                for (int u = 0; u < 4; u++) {
                    float s = vv[u];
                    if (s > ts[NCAND-1]) {
                        int ni = nb + 4*n4 + u;
#pragma unroll
                        for (int k = 0; k < NCAND; k++) {
                            if (s > ts[k]) {
                                float tv = ts[k]; ts[k] = s; s = tv;
                                int tn = ti[k]; ti[k] = ni; ni = tn;
                            }
                        }
                    }
                }
            }
        }
    }

    // ---- merge the two halves' top-8 lists
    __syncthreads();
    if (tid >= 128) {
#pragma unroll
        for (int k = 0; k < NCAND; k++) {
            Ss[tok][k] = ts[k];
            ((int*)&Ss[tok][16])[k] = ti[k];
        }
    }
    __syncthreads();
    if (tid < 128) {
#pragma unroll
        for (int k2 = 0; k2 < NCAND; k2++) {
            float s = Ss[tok][k2];
            int  ni = ((int*)&Ss[tok][16])[k2];
            if (s > ts[NCAND-1]) {
#pragma unroll
                for (int k = 0; k < NCAND; k++) {
                    if (s > ts[k]) {
                        float tv = ts[k]; ts[k] = s; s = tv;
                        int tn = ti[k]; ti[k] = ni; ni = tn;
                    }
                }
            }
        }
        int gtok = token0 + tok;
#pragma unroll
        for (int k = 0; k < NCAND; k++)
            g_ci[((size_t)gtok*NSPLIT4 + split)*NCAND + k] = ti[k];
    }
}

// ---------------- K4: fused exact fp32 rescore + softmax + V gather (2 tokens per block) ----------------
__global__ void rescore_gather_kernel(const float* __restrict__ kK,
                                      const float4* __restrict__ V4,
                                      float* __restrict__ out, int out_size) {
    int t0 = blockIdx.x * 2;
    __shared__ float qs[256];      // 2 Q rows (tokens t0, t0+1)
    __shared__ float ws[2][TK_];
    __shared__ int   is[2][TK_];
    int tid = threadIdx.x;

    qs[tid] = g_Q[(size_t)t0*R_ + tid];
    __syncthreads();

    if (tid < 64) {
        int wp   = tid >> 5;       // 0 or 1: which token
        int lane = tid & 31;
        int t = t0 + wp;
        int cand = g_ci[(size_t)t*32 + lane];
        const float4* kr = (const float4*)(kK + (size_t)cand*R_);
        const float* q = qs + wp*128;
        float acc = 0.f;
#pragma unroll
        for (int r4 = 0; r4 < 32; r4++) {
            float4 k4 = kr[r4];
            const float* q4 = q + 4*r4;
            acc = fmaf(q4[0], k4.x, acc);
            acc = fmaf(q4[1], k4.y, acc);
            acc = fmaf(q4[2], k4.z, acc);
            acc = fmaf(q4[3], k4.w, acc);
        }
        // warp-wide 8x (max, tie -> min index) selection
        float v = acc; int id = cand;
        float selv[TK_]; int seli[TK_];
#pragma unroll
        for (int k = 0; k < TK_; k++) {
            float bv = v; int bi = id;
#pragma unroll
            for (int off = 16; off > 0; off >>= 1) {
                float ov = __shfl_xor_sync(0xffffffffu, bv, off);
                int   oi = __shfl_xor_sync(0xffffffffu, bi, off);
                if (ov > bv || (ov == bv && oi < bi)) { bv = ov; bi = oi; }
            }
            selv[k] = bv; seli[k] = bi;
            if (id == bi) v = -3.402823466e38f;
        }
        float sv0 = selv[0] * SCALE_;
        float e[TK_]; float sum = 0.f;
#pragma unroll
        for (int k = 0; k < TK_; k++) { e[k] = expf(selv[k]*SCALE_ - sv0); sum += e[k]; }

        const int NBSD = B_*S_*D_;
        bool extended = (out_size >= NBSD + 2*NTOK*TK_);
        if (lane < TK_) {
            float w = e[lane] / sum;
            ws[wp][lane] = w;
            is[wp][lane] = seli[lane];
            if (extended) {
                out[NBSD + (size_t)t*TK_ + lane]            = (float)seli[lane];
                out[NBSD + NTOK*TK_ + (size_t)t*TK_ + lane] = w;
            }
        }
    }
    __syncthreads();

    // gather: each thread handles d4 = tid for BOTH tokens (2 x 8 independent loads)
    int d4 = tid;                 // 0..255
#pragma unroll
    for (int wp = 0; wp < 2; wp++) {
        float4 acc = make_float4(0.f, 0.f, 0.f, 0.f);
#pragma unroll
        for (int k = 0; k < TK_; k++) {
            float w  = ws[wp][k];
            float4 v = V4[(size_t)is[wp][k]*(D_/4) + d4];
            acc.x = fmaf(w, v.x, acc.x);
            acc.y = fmaf(w, v.y, acc.y);
            acc.z = fmaf(w, v.z, acc.z);
            acc.w = fmaf(w, v.w, acc.w);
        }
        ((float4*)out)[(size_t)(t0 + wp)*(D_/4) + d4] = acc;
    }
}

// ---------------- launch ----------------
extern "C" void kernel_launch(void* const* d_in, const int* in_sizes, int n_in,
                              void* d_out, int out_size) {
    const float* x  = (const float*)d_in[0];
    const float* mw = (const float*)d_in[1];
    const float* cn = (const float*)d_in[2];
    const float* kK = (const float*)d_in[3];
    const float* kV = (const float*)d_in[4];
    float* out = (float*)d_out;

    cudaFuncSetAttribute(score_mma_kernel, cudaFuncAttributeMaxDynamicSharedMemorySize, SMEM_SC);

    sc_kernel<<<dim3(B_, D_), R_>>>(mw, cn, (const float4*)kK);
    q_kernel<<<dim3(S_/64, B_), 256>>>(x);
    score_mma_kernel<<<dim3(NTOK/128, NSPLIT4), 256, SMEM_SC>>>();
    rescore_gather_kernel<<<NTOK/2, 256>>>(kK, (const float4*)kV, out, out_size);
}